// round 11
// baseline (speedup 1.0000x reference)
#include <cuda_runtime.h>
#include <math.h>

// ---------------------------------------------------------------------------
// ConsistencyLoss, single fused kernel, smem-staged streaming.
//   kl_i = C[idx] - sum_j T[idx][j]*x_ij + m_i + log(sum_j exp(x_ij - m_i))
//   idx  = target in {0,1,2} ? target : 3
// Inputs: [0] fatigue_logits (UNUSED), [1] emotion_logits [B,7] f32,
//         [2] fatigue_targets [B] int32.  Output: 1 float.
// ---------------------------------------------------------------------------

#define TPB        256
#define RPT        4
#define TILE_ROWS  (TPB * RPT)        // 1024 rows per block
#define TILE_F     (TILE_ROWS * 7)    // 7168 floats = 28 KB
#define MAX_BLOCKS 8192

struct Params {
    float t[4][7];
    float c[4];
};

__device__ float        g_part[MAX_BLOCKS];
__device__ unsigned int g_count = 0;

__global__ void __launch_bounds__(TPB)
kl_staged_kernel(const float* __restrict__ logits,
                 const int*   __restrict__ tgt,
                 float* __restrict__ out,
                 int nrows, Params P)
{
    __shared__ float s_log[TILE_F];       // 28 KB
    __shared__ int   s_tgt[TILE_ROWS];    // 4 KB
    __shared__ float sh_t[4][7];
    __shared__ float sh_c[4];
    __shared__ float sh_red[TPB / 32];
    __shared__ int   sh_last;

    const int tid = threadIdx.x;
    if (tid < 28) sh_t[tid / 7][tid % 7] = P.t[tid / 7][tid % 7];
    if (tid < 4)  sh_c[tid] = P.c[tid];

    const long long row0 = (long long)blockIdx.x * TILE_ROWS;
    const int rows = (int)min((long long)TILE_ROWS, (long long)nrows - row0);
    const int nf   = rows * 7;

    // ---- stage logits: coalesced float4 (tile base is 16B-aligned:
    //      row0*7*4 = blockIdx*28672, multiple of 16)
    {
        const float4* g4 = (const float4*)(logits + row0 * 7);
        float4* s4 = (float4*)s_log;
        const int nf4 = nf >> 2;
        #pragma unroll
        for (int i = 0; i < (TILE_F / 4 + TPB - 1) / TPB; i++) {   // 7 iters
            const int idx = i * TPB + tid;
            if (idx < nf4) s4[idx] = g4[idx];
        }
        for (int idx = (nf4 << 2) + tid; idx < nf; idx += TPB)    // <4 floats
            s_log[idx] = logits[row0 * 7 + idx];
    }
    // ---- stage targets: one int4 per thread
    {
        const int4* t4 = (const int4*)(tgt + row0);
        int4* st4 = (int4*)s_tgt;
        const int nt4 = rows >> 2;
        if (tid < nt4) st4[tid] = t4[tid];
        for (int idx = (nt4 << 2) + tid; idx < rows; idx += TPB)
            s_tgt[idx] = tgt[row0 + idx];
    }
    __syncthreads();

    // ---- compute: lane stride 7 in smem -> conflict-free
    float sum = 0.0f;
    #pragma unroll
    for (int k = 0; k < RPT; k++) {
        const int r = k * TPB + tid;
        if (r < rows) {
            float x[7];
            #pragma unroll
            for (int j = 0; j < 7; j++) x[j] = s_log[r * 7 + j];

            float m = x[0];
            #pragma unroll
            for (int j = 1; j < 7; j++) m = fmaxf(m, x[j]);

            float s = 0.0f;
            #pragma unroll
            for (int j = 0; j < 7; j++) s += __expf(x[j] - m);

            const int t = s_tgt[r];
            const int idx = (t >= 0 && t <= 2) ? t : 3;

            float dot = sh_c[idx];
            #pragma unroll
            for (int j = 0; j < 7; j++)
                dot = fmaf(-sh_t[idx][j], x[j], dot);   // C - sum T*x

            sum += dot + m + __logf(s);
        }
    }

    // ---- intra-block reduction
    const unsigned full = 0xFFFFFFFFu;
    #pragma unroll
    for (int off = 16; off > 0; off >>= 1)
        sum += __shfl_down_sync(full, sum, off);
    const int wid = tid >> 5, lane = tid & 31;
    if (lane == 0) sh_red[wid] = sum;
    __syncthreads();
    if (wid == 0) {
        float v = (lane < TPB / 32) ? sh_red[lane] : 0.0f;
        #pragma unroll
        for (int off = (TPB / 64); off > 0; off >>= 1)
            v += __shfl_down_sync(full, v, off);
        if (lane == 0) g_part[blockIdx.x] = v;
    }

    // ---- completion counter: last block finalizes
    __threadfence();
    if (tid == 0) {
        const unsigned v = atomicAdd(&g_count, 1u);
        sh_last = (v == gridDim.x - 1) ? 1 : 0;
    }
    __syncthreads();

    if (sh_last) {
        __threadfence();
        const int npart = gridDim.x;
        double d = 0.0;
        for (int i = tid; i < npart; i += TPB)
            d += (double)__ldcg(&g_part[i]);
        #pragma unroll
        for (int off = 16; off > 0; off >>= 1)
            d += __shfl_down_sync(full, d, off);
        __shared__ double sh_d[TPB / 32];
        if (lane == 0) sh_d[wid] = d;
        __syncthreads();
        if (wid == 0) {
            double w = (lane < TPB / 32) ? sh_d[lane] : 0.0;
            #pragma unroll
            for (int off = (TPB / 64); off > 0; off >>= 1)
                w += __shfl_down_sync(full, w, off);
            if (lane == 0) {
                out[0] = (float)(w / (double)nrows);
                g_count = 0;   // reset for next graph replay
            }
        }
    }
}

extern "C" void kernel_launch(void* const* d_in, const int* in_sizes, int n_in,
                              void* d_out, int out_size)
{
    const float* emotion = (const float*)d_in[1];   // [B,7]
    const int*   targets = (const int*)d_in[2];     // [B]
    const int nrows = in_sizes[2];

    static const float TBL[4][7] = {
        {0.05f, 0.02f, 0.03f, 0.4f, 0.05f, 0.4f, 0.05f},
        {0.05f, 0.05f, 0.05f, 0.05f, 0.3f, 0.05f, 0.45f},
        {0.1f, 0.15f, 0.2f, 0.02f, 0.35f, 0.03f, 0.15f},
        {1.0f/7.0f, 1.0f/7.0f, 1.0f/7.0f, 1.0f/7.0f, 1.0f/7.0f, 1.0f/7.0f, 1.0f/7.0f},
    };
    Params P;
    for (int r = 0; r < 4; r++) {
        float tr[7], s = 0.0f;
        for (int j = 0; j < 7; j++) { tr[j] = TBL[r][j] + 1e-8f; s += tr[j]; }
        float c = 0.0f;
        for (int j = 0; j < 7; j++) {
            const float t = tr[j] / s;
            P.t[r][j] = t;
            c += t * logf(t);
        }
        P.c[r] = c;
    }

    int blocks = (int)(((long long)nrows + TILE_ROWS - 1) / TILE_ROWS);  // 3907
    if (blocks > MAX_BLOCKS) blocks = MAX_BLOCKS;
    kl_staged_kernel<<<blocks, TPB>>>(emotion, targets, (float*)d_out, nrows, P);
}

// round 14
// speedup vs baseline: 1.0406x; 1.0406x over previous
#include <cuda_runtime.h>
#include <math.h>

// ---------------------------------------------------------------------------
// ConsistencyLoss, single fused kernel, smem-staged streaming.
//   kl_i = C[idx] - sum_j T[idx][j]*x_ij + m_i + log(sum_j exp(x_ij - m_i))
//   idx  = target in {0,1,2} ? target : 3
// Inputs: [0] fatigue_logits (UNUSED), [1] emotion_logits [B,7] f32,
//         [2] fatigue_targets [B] int32.  Output: 1 float.
// ---------------------------------------------------------------------------

#define TPB        256
#define RPT        4
#define TILE_ROWS  (TPB * RPT)        // 1024 rows per block
#define TILE_F     (TILE_ROWS * 7)    // 7168 floats = 28 KB
#define MAX_BLOCKS 8192

struct Params {
    float t[4][7];
    float c[4];
};

__device__ float        g_part[MAX_BLOCKS];
__device__ unsigned int g_count = 0;

__global__ void __launch_bounds__(TPB)
kl_staged_kernel(const float* __restrict__ logits,
                 const int*   __restrict__ tgt,
                 float* __restrict__ out,
                 int nrows, Params P)
{
    __shared__ float s_log[TILE_F];       // 28 KB
    __shared__ int   s_tgt[TILE_ROWS];    // 4 KB
    __shared__ float sh_t[4][7];
    __shared__ float sh_c[4];
    __shared__ float sh_red[TPB / 32];
    __shared__ int   sh_last;

    const int tid = threadIdx.x;
    if (tid < 28) sh_t[tid / 7][tid % 7] = P.t[tid / 7][tid % 7];
    if (tid < 4)  sh_c[tid] = P.c[tid];

    const long long row0 = (long long)blockIdx.x * TILE_ROWS;
    const int rows = (int)min((long long)TILE_ROWS, (long long)nrows - row0);
    const int nf   = rows * 7;

    // ---- stage logits: coalesced float4 (tile base is 16B-aligned:
    //      row0*7*4 = blockIdx*28672, multiple of 16)
    {
        const float4* g4 = (const float4*)(logits + row0 * 7);
        float4* s4 = (float4*)s_log;
        const int nf4 = nf >> 2;
        #pragma unroll
        for (int i = 0; i < (TILE_F / 4 + TPB - 1) / TPB; i++) {   // 7 iters
            const int idx = i * TPB + tid;
            if (idx < nf4) s4[idx] = g4[idx];
        }
        for (int idx = (nf4 << 2) + tid; idx < nf; idx += TPB)    // <4 floats
            s_log[idx] = logits[row0 * 7 + idx];
    }
    // ---- stage targets: one int4 per thread
    {
        const int4* t4 = (const int4*)(tgt + row0);
        int4* st4 = (int4*)s_tgt;
        const int nt4 = rows >> 2;
        if (tid < nt4) st4[tid] = t4[tid];
        for (int idx = (nt4 << 2) + tid; idx < rows; idx += TPB)
            s_tgt[idx] = tgt[row0 + idx];
    }
    __syncthreads();

    // ---- compute: lane stride 7 in smem -> conflict-free
    float sum = 0.0f;
    #pragma unroll
    for (int k = 0; k < RPT; k++) {
        const int r = k * TPB + tid;
        if (r < rows) {
            float x[7];
            #pragma unroll
            for (int j = 0; j < 7; j++) x[j] = s_log[r * 7 + j];

            float m = x[0];
            #pragma unroll
            for (int j = 1; j < 7; j++) m = fmaxf(m, x[j]);

            float s = 0.0f;
            #pragma unroll
            for (int j = 0; j < 7; j++) s += __expf(x[j] - m);

            const int t = s_tgt[r];
            const int idx = (t >= 0 && t <= 2) ? t : 3;

            float dot = sh_c[idx];
            #pragma unroll
            for (int j = 0; j < 7; j++)
                dot = fmaf(-sh_t[idx][j], x[j], dot);   // C - sum T*x

            sum += dot + m + __logf(s);
        }
    }

    // ---- intra-block reduction
    const unsigned full = 0xFFFFFFFFu;
    #pragma unroll
    for (int off = 16; off > 0; off >>= 1)
        sum += __shfl_down_sync(full, sum, off);
    const int wid = tid >> 5, lane = tid & 31;
    if (lane == 0) sh_red[wid] = sum;
    __syncthreads();
    if (wid == 0) {
        float v = (lane < TPB / 32) ? sh_red[lane] : 0.0f;
        #pragma unroll
        for (int off = (TPB / 64); off > 0; off >>= 1)
            v += __shfl_down_sync(full, v, off);
        if (lane == 0) g_part[blockIdx.x] = v;
    }

    // ---- completion counter: last block finalizes
    __threadfence();
    if (tid == 0) {
        const unsigned v = atomicAdd(&g_count, 1u);
        sh_last = (v == gridDim.x - 1) ? 1 : 0;
    }
    __syncthreads();

    if (sh_last) {
        __threadfence();
        const int npart = gridDim.x;
        double d = 0.0;
        for (int i = tid; i < npart; i += TPB)
            d += (double)__ldcg(&g_part[i]);
        #pragma unroll
        for (int off = 16; off > 0; off >>= 1)
            d += __shfl_down_sync(full, d, off);
        __shared__ double sh_d[TPB / 32];
        if (lane == 0) sh_d[wid] = d;
        __syncthreads();
        if (wid == 0) {
            double w = (lane < TPB / 32) ? sh_d[lane] : 0.0;
            #pragma unroll
            for (int off = (TPB / 64); off > 0; off >>= 1)
                w += __shfl_down_sync(full, w, off);
            if (lane == 0) {
                out[0] = (float)(w / (double)nrows);
                g_count = 0;   // reset for next graph replay
            }
        }
    }
}

extern "C" void kernel_launch(void* const* d_in, const int* in_sizes, int n_in,
                              void* d_out, int out_size)
{
    const float* emotion = (const float*)d_in[1];   // [B,7]
    const int*   targets = (const int*)d_in[2];     // [B]
    const int nrows = in_sizes[2];

    static const float TBL[4][7] = {
        {0.05f, 0.02f, 0.03f, 0.4f, 0.05f, 0.4f, 0.05f},
        {0.05f, 0.05f, 0.05f, 0.05f, 0.3f, 0.05f, 0.45f},
        {0.1f, 0.15f, 0.2f, 0.02f, 0.35f, 0.03f, 0.15f},
        {1.0f/7.0f, 1.0f/7.0f, 1.0f/7.0f, 1.0f/7.0f, 1.0f/7.0f, 1.0f/7.0f, 1.0f/7.0f},
    };
    Params P;
    for (int r = 0; r < 4; r++) {
        float tr[7], s = 0.0f;
        for (int j = 0; j < 7; j++) { tr[j] = TBL[r][j] + 1e-8f; s += tr[j]; }
        float c = 0.0f;
        for (int j = 0; j < 7; j++) {
            const float t = tr[j] / s;
            P.t[r][j] = t;
            c += t * logf(t);
        }
        P.c[r] = c;
    }

    int blocks = (int)(((long long)nrows + TILE_ROWS - 1) / TILE_ROWS);  // 3907
    if (blocks > MAX_BLOCKS) blocks = MAX_BLOCKS;
    kl_staged_kernel<<<blocks, TPB>>>(emotion, targets, (float*)d_out, nrows, P);
}